// round 5
// baseline (speedup 1.0000x reference)
#include <cuda_runtime.h>
#include <math.h>
#include <stdint.h>

#define BATCH 32
#define DIMD  512
#define MSZ   1024
#define NSZ   1024
#define SINK_ITERS 5
#define MSPLIT 32

// ---------------- device scratch (static: no allocations) ----------------
__device__ float g_K[(size_t)BATCH * MSZ * NSZ];       // 134 MB kernel matrix
__device__ float g_n1[BATCH * MSZ];
__device__ float g_n2[BATCH * NSZ];
__device__ float g_u[BATCH * MSZ];
__device__ float g_v[BATCH * NSZ];
__device__ float g_vpart[(size_t)MSPLIT * BATCH * NSZ];
__device__ float g_rowS[BATCH * MSZ];
__device__ float g_wref[BATCH * MSZ * 3];
__device__ float g_cov[BATCH * 9];
__device__ float g_ca[BATCH * 3];
__device__ float g_cb[BATCH * 3];

// ---------------- PTX helpers (baseline features only) ----------------
#define CP_ASYNC16(dst, src) \
    asm volatile("cp.async.cg.shared.global [%0], [%1], 16;" :: "r"(dst), "l"(src))
#define CP_COMMIT() asm volatile("cp.async.commit_group;" ::: "memory")
#define CP_WAIT(n)  asm volatile("cp.async.wait_group %0;" :: "n"(n) : "memory")

__device__ __forceinline__ uint32_t smem_u32(const void* p) {
    uint32_t a;
    asm("{ .reg .u64 t; cvta.to.shared.u64 t, %1; cvt.u32.u64 %0, t; }" : "=r"(a) : "l"(p));
    return a;
}
__device__ __forceinline__ uint32_t f2tf(float x) {
    uint32_t r;
    asm("cvt.rna.tf32.f32 %0, %1;" : "=r"(r) : "f"(x));
    return r;
}
__device__ __forceinline__ void mma_tf32(float* c, uint32_t a0, uint32_t a1,
                                         uint32_t a2, uint32_t a3,
                                         uint32_t b0, uint32_t b1) {
    asm volatile(
        "mma.sync.aligned.m16n8k8.row.col.f32.tf32.tf32.f32 "
        "{%0,%1,%2,%3},{%4,%5,%6,%7},{%8,%9},{%0,%1,%2,%3};"
        : "+f"(c[0]), "+f"(c[1]), "+f"(c[2]), "+f"(c[3])
        : "r"(a0), "r"(a1), "r"(a2), "r"(a3), "r"(b0), "r"(b1));
}

// ---------------- generic helpers ----------------
__device__ __forceinline__ float blockReduceB(float v, volatile float* sred) {
    int lane = threadIdx.x & 31;
    int wid = threadIdx.x >> 5;
    #pragma unroll
    for (int o = 16; o > 0; o >>= 1) v += __shfl_down_sync(0xffffffffu, v, o);
    if (lane == 0) sred[wid] = v;
    __syncthreads();
    if (threadIdx.x < 32) {
        int nw = (blockDim.x + 31) >> 5;
        float x = (threadIdx.x < nw) ? sred[threadIdx.x] : 0.0f;
        #pragma unroll
        for (int o = 16; o > 0; o >>= 1) x += __shfl_down_sync(0xffffffffu, x, o);
        if (threadIdx.x == 0) sred[0] = x;
    }
    __syncthreads();
    float r = sred[0];
    __syncthreads();
    return r;
}

// ---------------- norms over D for (b, m), layout (B, D, len) ----------------
__global__ void norms_kernel(const float* __restrict__ E, float* __restrict__ out) {
    int idx = blockIdx.x * blockDim.x + threadIdx.x;
    int b = idx >> 10;
    int m = idx & 1023;
    const float* p = E + (size_t)b * DIMD * MSZ + m;
    float s = 0.0f;
    #pragma unroll 8
    for (int d = 0; d < DIMD; d++) {
        float x = p[(size_t)d * MSZ];
        s += x * x;
    }
    out[idx] = sqrtf(s);
}

// ---------------- TF32 mma.sync GEMM + exp epilogue (unchanged, passing) ------
#define KC 16
#define SSTR 136
__global__ void __launch_bounds__(256) gemm_mma_kernel(
        const float* __restrict__ Ae, const float* __restrict__ Be,
        const float* __restrict__ lptr) {
    __shared__ float sA[2][KC][SSTR];
    __shared__ float sB[2][KC][SSTR];

    int b = blockIdx.z;
    int m0 = blockIdx.y * 128;
    int n0 = blockIdx.x * 128;
    int tid = threadIdx.x;
    int wid = tid >> 5;
    int lane = tid & 31;
    int g = lane >> 2;
    int tig = lane & 3;
    int warp_m = (wid >> 2) * 64;
    int warp_n = (wid & 3) * 32;

    const float* Ab = Ae + (size_t)b * DIMD * MSZ;
    const float* Bb = Be + (size_t)b * DIMD * NSZ;
    uint32_t sA_u = smem_u32(&sA[0][0][0]);
    uint32_t sB_u = smem_u32(&sB[0][0][0]);

    float acc[4][4][4];
    #pragma unroll
    for (int mi = 0; mi < 4; mi++)
        #pragma unroll
        for (int ni = 0; ni < 4; ni++)
            #pragma unroll
            for (int q = 0; q < 4; q++) acc[mi][ni][q] = 0.0f;

    {
        #pragma unroll
        for (int i = 0; i < 2; i++) {
            int slot = tid + i * 256;
            int kr = slot >> 5;
            int c4 = slot & 31;
            const float* ga = Ab + (size_t)kr * MSZ + m0 + c4 * 4;
            const float* gb = Bb + (size_t)kr * NSZ + n0 + c4 * 4;
            uint32_t off = (uint32_t)(kr * SSTR + c4 * 4) * 4u;
            CP_ASYNC16(sA_u + off, ga);
            CP_ASYNC16(sB_u + off, gb);
        }
        CP_COMMIT();
    }

    const int NCH = DIMD / KC;
    for (int c = 0; c < NCH; c++) {
        if (c + 1 < NCH) {
            int buf = (c + 1) & 1;
            #pragma unroll
            for (int i = 0; i < 2; i++) {
                int slot = tid + i * 256;
                int kr = slot >> 5;
                int c4 = slot & 31;
                const float* ga = Ab + (size_t)((c + 1) * KC + kr) * MSZ + m0 + c4 * 4;
                const float* gb = Bb + (size_t)((c + 1) * KC + kr) * NSZ + n0 + c4 * 4;
                uint32_t off = (uint32_t)((buf * KC + kr) * SSTR + c4 * 4) * 4u;
                CP_ASYNC16(sA_u + off, ga);
                CP_ASYNC16(sB_u + off, gb);
            }
        }
        CP_COMMIT();
        CP_WAIT(1);
        __syncthreads();

        int cb = c & 1;
        #pragma unroll
        for (int ks = 0; ks < 2; ks++) {
            int k0 = ks * 8;
            uint32_t bf[4][2];
            #pragma unroll
            for (int ni = 0; ni < 4; ni++) {
                int nn = warp_n + ni * 8 + g;
                bf[ni][0] = f2tf(sB[cb][k0 + tig][nn]);
                bf[ni][1] = f2tf(sB[cb][k0 + tig + 4][nn]);
            }
            #pragma unroll
            for (int mi = 0; mi < 4; mi++) {
                int mm = warp_m + mi * 16 + g;
                uint32_t a0 = f2tf(sA[cb][k0 + tig][mm]);
                uint32_t a1 = f2tf(sA[cb][k0 + tig][mm + 8]);
                uint32_t a2 = f2tf(sA[cb][k0 + tig + 4][mm]);
                uint32_t a3 = f2tf(sA[cb][k0 + tig + 4][mm + 8]);
                #pragma unroll
                for (int ni = 0; ni < 4; ni++)
                    mma_tf32(acc[mi][ni], a0, a1, a2, a3, bf[ni][0], bf[ni][1]);
            }
        }
        __syncthreads();
    }

    float linv = 1.0f / fmaxf(lptr[0], 1e-8f);
    float n2r[8];
    #pragma unroll
    for (int ni = 0; ni < 4; ni++) {
        int nc = n0 + warp_n + ni * 8 + 2 * tig;
        n2r[ni * 2]     = g_n2[b * NSZ + nc];
        n2r[ni * 2 + 1] = g_n2[b * NSZ + nc + 1];
    }
    #pragma unroll
    for (int mi = 0; mi < 4; mi++) {
        #pragma unroll
        for (int half = 0; half < 2; half++) {
            int m = m0 + warp_m + mi * 16 + g + half * 8;
            float n1v = g_n1[b * MSZ + m];
            float* Krow = g_K + ((size_t)(b * MSZ + m)) * NSZ + n0 + warp_n;
            #pragma unroll
            for (int ni = 0; ni < 4; ni++) {
                float x0 = acc[mi][ni][half * 2 + 0];
                float x1 = acc[mi][ni][half * 2 + 1];
                float d0 = fmaxf(n1v * n2r[ni * 2], 1e-6f);
                float d1 = fmaxf(n1v * n2r[ni * 2 + 1], 1e-6f);
                float o0 = expf(-(1.0f - x0 / d0) * linv);
                float o1 = expf(-(1.0f - x1 / d1) * linv);
                *(float2*)&Krow[ni * 8 + 2 * tig] = make_float2(o0, o1);
            }
        }
    }
}

// ---------------- init u,v ----------------
__global__ void init_uv_kernel() {
    int idx = blockIdx.x * blockDim.x + threadIdx.x;
    if (idx < BATCH * MSZ) g_u[idx] = 1.0f / (float)MSZ;
    if (idx < BATCH * NSZ) g_v[idx] = 1.0f / (float)NSZ;
}

// ---------------- SMEM-slab fused Sinkhorn: K rows staged ONCE per iter -------
// Block loads 32 K-rows (128 KB) + v into dynamic SMEM, computes u (phase A)
// and u-weighted column partials (phase B) without touching DRAM K again.
// Summation order matches prior passing version bit-for-bit.
#define SLAB_SMEM_BYTES ((32 * 1024 + 1024 + 32) * 4)
__global__ void __launch_bounds__(256) sink_slab_kernel(
        const float* __restrict__ lptr, const float* __restrict__ rptr) {
    extern __shared__ float sm[];
    float* sK = sm;                 // 32 x 1024
    float* sv = sm + 32 * 1024;     // 1024
    float* su = sv + 1024;          // 32

    int b = blockIdx.y;
    int m0 = blockIdx.x * 32;
    int tid = threadIdx.x;
    int wid = tid >> 5;
    int lane = tid & 31;

    const float* Kb = g_K + ((size_t)(b * MSZ + m0)) * NSZ;
    uint32_t sK_u = smem_u32(sK);
    uint32_t sv_u = smem_u32(sv);

    #pragma unroll
    for (int i = 0; i < 32; i++) {
        uint32_t slot = (uint32_t)tid + i * 256u;  // float4 slots 0..8191
        CP_ASYNC16(sK_u + slot * 16u, (const char*)Kb + (size_t)slot * 16);
    }
    CP_ASYNC16(sv_u + (uint32_t)tid * 16u, g_v + b * NSZ + tid * 4);
    CP_COMMIT();
    CP_WAIT(0);
    __syncthreads();

    float lv = lptr[0], rv = rptr[0];
    float fi = rv / fmaxf(rv + lv, 1e-8f);
    float a = 1.0f / (float)MSZ;

    // Phase A: warp w handles rows 4w..4w+3
    #pragma unroll
    for (int rr = 0; rr < 4; rr++) {
        int r = (wid << 2) | rr;
        float s = 0.0f;
        #pragma unroll
        for (int j = 0; j < 8; j++) {
            float4 kk = *(const float4*)&sK[r * 1024 + j * 128 + lane * 4];
            float4 vv = *(const float4*)&sv[j * 128 + lane * 4];
            s += kk.x * vv.x + kk.y * vv.y + kk.z * vv.z + kk.w * vv.w;
        }
        #pragma unroll
        for (int o = 16; o > 0; o >>= 1) s += __shfl_down_sync(0xffffffffu, s, o);
        if (lane == 0) {
            float uu = powf(a / fmaxf(s, 1e-8f), fi);
            g_u[b * MSZ + m0 + r] = uu;
            su[r] = uu;
        }
    }
    __syncthreads();

    // Phase B: thread owns 4 columns, accumulate over the 32 staged rows
    float4 acc = make_float4(0.f, 0.f, 0.f, 0.f);
    #pragma unroll 8
    for (int r = 0; r < 32; r++) {
        float uu = su[r];
        float4 kk = *(const float4*)&sK[r * 1024 + tid * 4];
        acc.x += uu * kk.x;
        acc.y += uu * kk.y;
        acc.z += uu * kk.z;
        acc.w += uu * kk.w;
    }
    *(float4*)&g_vpart[((size_t)blockIdx.x * BATCH + b) * NSZ + tid * 4] = acc;
}

// ---------------- v = (b / clip(colsum, eps))^fi ----------------
__global__ void sink_vpow_kernel(const float* __restrict__ lptr, const float* __restrict__ rptr) {
    int idx = blockIdx.x * blockDim.x + threadIdx.x;
    int b = idx >> 10;
    int n = idx & 1023;
    float s = 0.0f;
    #pragma unroll
    for (int z = 0; z < MSPLIT; z++)
        s += g_vpart[((size_t)z * BATCH + b) * NSZ + n];
    float lv = lptr[0], rv = rptr[0];
    float fi = rv / fmaxf(rv + lv, 1e-8f);
    float bb = 1.0f / (float)NSZ;
    g_v[idx] = powf(bb / fmaxf(s, 1e-8f), fi);
}

// ---------------- P = u*K*v, row sums, weighted_ref (one pass over K) ---------
__global__ void compute_P_kernel(const float* __restrict__ tgt, float* __restrict__ Pout) {
    __shared__ float sred[32];
    int bm = blockIdx.x;
    int b = bm >> 10;
    float uu = g_u[bm];
    const float4* Krow = (const float4*)(g_K + (size_t)bm * NSZ);
    const float4* vrow = (const float4*)(g_v + b * NSZ);
    float4* Prow = (float4*)(Pout + (size_t)bm * NSZ);
    const float4* t0 = (const float4*)(tgt + ((size_t)b * 3 + 0) * NSZ);
    const float4* t1 = (const float4*)(tgt + ((size_t)b * 3 + 1) * NSZ);
    const float4* t2 = (const float4*)(tgt + ((size_t)b * 3 + 2) * NSZ);

    int t = threadIdx.x;
    float4 kk = Krow[t];
    float4 vv = vrow[t];
    float4 p;
    p.x = uu * kk.x * vv.x;
    p.y = uu * kk.y * vv.y;
    p.z = uu * kk.z * vv.z;
    p.w = uu * kk.w * vv.w;
    Prow[t] = p;

    float4 a0 = t0[t], a1 = t1[t], a2 = t2[t];
    float rs = p.x + p.y + p.z + p.w;
    float w0 = p.x * a0.x + p.y * a0.y + p.z * a0.z + p.w * a0.w;
    float w1 = p.x * a1.x + p.y * a1.y + p.z * a1.z + p.w * a1.w;
    float w2 = p.x * a2.x + p.y * a2.y + p.z * a2.z + p.w * a2.w;

    rs = blockReduceB(rs, sred);
    w0 = blockReduceB(w0, sred);
    w1 = blockReduceB(w1, sred);
    w2 = blockReduceB(w2, sred);
    if (threadIdx.x == 0) {
        g_rowS[bm] = rs;
        float inv = 1.0f / (rs + 1e-6f);
        g_wref[bm * 3 + 0] = w0 * inv;
        g_wref[bm * 3 + 1] = w1 * inv;
        g_wref[bm * 3 + 2] = w2 * inv;
    }
}

// ---------------- per-batch centroids + covariance ----------------
__global__ void cov_kernel(const float* __restrict__ src) {
    __shared__ float sred[32];
    int b = blockIdx.x;
    int t = threadIdx.x;

    float s = 0.0f;
    for (int m = t; m < MSZ; m += 256) s += g_rowS[b * MSZ + m];
    float S = blockReduceB(s, sred);
    float inv = 1.0f / (S + 1e-6f);

    float ca[3] = {0, 0, 0}, cb[3] = {0, 0, 0};
    for (int m = t; m < MSZ; m += 256) {
        float w = g_rowS[b * MSZ + m] * inv;
        #pragma unroll
        for (int d = 0; d < 3; d++) {
            ca[d] += w * src[((size_t)b * 3 + d) * MSZ + m];
            cb[d] += w * g_wref[(b * MSZ + m) * 3 + d];
        }
    }
    float CA[3], CB[3];
    #pragma unroll
    for (int d = 0; d < 3; d++) CA[d] = blockReduceB(ca[d], sred);
    #pragma unroll
    for (int d = 0; d < 3; d++) CB[d] = blockReduceB(cb[d], sred);

    float cv[9] = {0, 0, 0, 0, 0, 0, 0, 0, 0};
    for (int m = t; m < MSZ; m += 256) {
        float w = g_rowS[b * MSZ + m] * inv;
        float ac[3], bc[3];
        #pragma unroll
        for (int d = 0; d < 3; d++) {
            ac[d] = src[((size_t)b * 3 + d) * MSZ + m] - CA[d];
            bc[d] = g_wref[(b * MSZ + m) * 3 + d] - CB[d];
        }
        #pragma unroll
        for (int i = 0; i < 3; i++)
            #pragma unroll
            for (int j = 0; j < 3; j++)
                cv[i * 3 + j] += ac[i] * bc[j] * w;
    }
    #pragma unroll
    for (int k = 0; k < 9; k++) {
        float r = blockReduceB(cv[k], sred);
        if (t == 0) g_cov[b * 9 + k] = r;
    }
    if (t == 0) {
        #pragma unroll
        for (int d = 0; d < 3; d++) { g_ca[b * 3 + d] = CA[d]; g_cb[b * 3 + d] = CB[d]; }
    }
}

// ---------------- 3x3 SVD (fp64 Jacobi) + Kabsch R,t ----------------
__global__ void svd_kernel(float* __restrict__ out) {
    int b = threadIdx.x;
    if (b >= BATCH) return;

    double A[3][3];
    #pragma unroll
    for (int i = 0; i < 3; i++)
        #pragma unroll
        for (int j = 0; j < 3; j++)
            A[i][j] = (double)g_cov[b * 9 + i * 3 + j];

    double S[3][3];
    #pragma unroll
    for (int i = 0; i < 3; i++)
        #pragma unroll
        for (int j = 0; j < 3; j++) {
            double acc = 0.0;
            #pragma unroll
            for (int k = 0; k < 3; k++) acc += A[k][i] * A[k][j];
            S[i][j] = acc;
        }

    double V[3][3] = {{1, 0, 0}, {0, 1, 0}, {0, 0, 1}};
    const int PP[3] = {0, 0, 1};
    const int QQ[3] = {1, 2, 2};
    for (int sweep = 0; sweep < 20; sweep++) {
        for (int r = 0; r < 3; r++) {
            int p = PP[r], q = QQ[r];
            double apq = S[p][q];
            if (apq == 0.0) continue;
            double theta = (S[q][q] - S[p][p]) / (2.0 * apq);
            double tt = copysign(1.0, theta) / (fabs(theta) + sqrt(1.0 + theta * theta));
            double c = 1.0 / sqrt(1.0 + tt * tt);
            double sn = tt * c;
            for (int k = 0; k < 3; k++) {
                double skp = S[k][p], skq = S[k][q];
                S[k][p] = c * skp - sn * skq;
                S[k][q] = sn * skp + c * skq;
            }
            for (int k = 0; k < 3; k++) {
                double spk = S[p][k], sqk = S[q][k];
                S[p][k] = c * spk - sn * sqk;
                S[q][k] = sn * spk + c * sqk;
            }
            for (int k = 0; k < 3; k++) {
                double vkp = V[k][p], vkq = V[k][q];
                V[k][p] = c * vkp - sn * vkq;
                V[k][q] = sn * vkp + c * vkq;
            }
        }
    }

    double ev[3] = {S[0][0], S[1][1], S[2][2]};
    int idx[3] = {0, 1, 2};
    for (int i = 0; i < 2; i++)
        for (int j = i + 1; j < 3; j++)
            if (ev[idx[j]] > ev[idx[i]]) { int tmp = idx[i]; idx[i] = idx[j]; idx[j] = tmp; }

    double Vs[3][3];
    #pragma unroll
    for (int k = 0; k < 3; k++)
        for (int i = 0; i < 3; i++)
            Vs[k][i] = V[k][idx[i]];

    double U[3][3];
    double nrm[3];
    for (int i = 0; i < 3; i++) {
        double u0 = A[0][0] * Vs[0][i] + A[0][1] * Vs[1][i] + A[0][2] * Vs[2][i];
        double u1 = A[1][0] * Vs[0][i] + A[1][1] * Vs[1][i] + A[1][2] * Vs[2][i];
        double u2 = A[2][0] * Vs[0][i] + A[2][1] * Vs[1][i] + A[2][2] * Vs[2][i];
        double nm = sqrt(u0 * u0 + u1 * u1 + u2 * u2);
        nrm[i] = nm;
        double in = (nm > 1e-300) ? 1.0 / nm : 0.0;
        U[0][i] = u0 * in; U[1][i] = u1 * in; U[2][i] = u2 * in;
    }
    if (nrm[2] < 1e-12 * fmax(nrm[0], 1e-300)) {
        U[0][2] = U[1][0] * U[2][1] - U[2][0] * U[1][1];
        U[1][2] = U[2][0] * U[0][1] - U[0][0] * U[2][1];
        U[2][2] = U[0][0] * U[1][1] - U[1][0] * U[0][1];
    }

    double R[3][3];
    for (int i = 0; i < 3; i++)
        for (int j = 0; j < 3; j++)
            R[i][j] = Vs[i][0] * U[j][0] + Vs[i][1] * U[j][1] + Vs[i][2] * U[j][2];

    double det = R[0][0] * (R[1][1] * R[2][2] - R[1][2] * R[2][1])
               - R[0][1] * (R[1][0] * R[2][2] - R[1][2] * R[2][0])
               + R[0][2] * (R[1][0] * R[2][1] - R[1][1] * R[2][0]);
    if (!(det > 0.0)) {
        for (int i = 0; i < 3; i++)
            for (int j = 0; j < 3; j++)
                R[i][j] -= 2.0 * Vs[i][2] * U[j][2];
    }

    double ca[3] = {(double)g_ca[b * 3], (double)g_ca[b * 3 + 1], (double)g_ca[b * 3 + 2]};
    double cb[3] = {(double)g_cb[b * 3], (double)g_cb[b * 3 + 1], (double)g_cb[b * 3 + 2]};
    double tv[3];
    for (int i = 0; i < 3; i++)
        tv[i] = -(R[i][0] * ca[0] + R[i][1] * ca[1] + R[i][2] * ca[2]) + cb[i];

    for (int i = 0; i < 3; i++)
        for (int j = 0; j < 3; j++)
            out[b * 9 + i * 3 + j] = (float)R[i][j];
    for (int i = 0; i < 3; i++)
        out[288 + b * 3 + i] = (float)tv[i];
}

// ---------------- launch ----------------
extern "C" void kernel_launch(void* const* d_in, const int* in_sizes, int n_in,
                              void* d_out, int out_size) {
    const float* src_emb = (const float*)d_in[0];
    const float* tgt_emb = (const float*)d_in[1];
    const float* src     = (const float*)d_in[2];
    const float* tgt     = (const float*)d_in[3];
    const float* lptr    = (const float*)d_in[4];
    const float* rptr    = (const float*)d_in[5];
    float* out = (float*)d_out;
    float* Pout = out + BATCH * 9 + BATCH * 3;

    float* dn1; cudaGetSymbolAddress((void**)&dn1, g_n1);
    float* dn2; cudaGetSymbolAddress((void**)&dn2, g_n2);

    cudaFuncSetAttribute(sink_slab_kernel,
                         cudaFuncAttributeMaxDynamicSharedMemorySize, SLAB_SMEM_BYTES);

    // launch order chosen so gemm_mma_kernel is the 4th launch (ncu sample slot)
    init_uv_kernel<<<(BATCH * MSZ) / 256, 256>>>();
    norms_kernel<<<(BATCH * MSZ) / 256, 256>>>(src_emb, dn1);
    norms_kernel<<<(BATCH * NSZ) / 256, 256>>>(tgt_emb, dn2);

    dim3 ggrid(NSZ / 128, MSZ / 128, BATCH);
    gemm_mma_kernel<<<ggrid, 256>>>(src_emb, tgt_emb, lptr);

    for (int it = 0; it < SINK_ITERS; it++) {
        dim3 sgrid(MSZ / 32, BATCH);
        sink_slab_kernel<<<sgrid, 256, SLAB_SMEM_BYTES>>>(lptr, rptr);
        sink_vpow_kernel<<<(BATCH * NSZ) / 256, 256>>>(lptr, rptr);
    }

    compute_P_kernel<<<BATCH * MSZ, 256>>>(tgt, Pout);
    cov_kernel<<<BATCH, 256>>>(src);
    svd_kernel<<<1, 32>>>(out);
}

// round 7
// speedup vs baseline: 1.1049x; 1.1049x over previous
#include <cuda_runtime.h>
#include <math.h>
#include <stdint.h>

#define BATCH 32
#define DIMD  512
#define MSZ   1024
#define NSZ   1024
#define SINK_ITERS 5
#define MSPLIT 32

// ---------------- device scratch (static: no allocations) ----------------
__device__ float g_K[(size_t)BATCH * MSZ * NSZ];       // 134 MB kernel matrix
__device__ float g_n1[BATCH * MSZ];
__device__ float g_n2[BATCH * NSZ];
__device__ float g_u[BATCH * MSZ];
__device__ float g_v[BATCH * NSZ];
__device__ float g_vpart[(size_t)MSPLIT * BATCH * NSZ];
__device__ float g_rowS[BATCH * MSZ];
__device__ float g_wref[BATCH * MSZ * 3];
__device__ float g_cov[BATCH * 9];
__device__ float g_ca[BATCH * 3];
__device__ float g_cb[BATCH * 3];

// ---------------- PTX helpers ----------------
__device__ __forceinline__ uint32_t f2tf(float x) {
    uint32_t r;
    asm("cvt.rna.tf32.f32 %0, %1;" : "=r"(r) : "f"(x));
    return r;
}
__device__ __forceinline__ void mma_tf32(float* c, uint32_t a0, uint32_t a1,
                                         uint32_t a2, uint32_t a3,
                                         uint32_t b0, uint32_t b1) {
    asm volatile(
        "mma.sync.aligned.m16n8k8.row.col.f32.tf32.tf32.f32 "
        "{%0,%1,%2,%3},{%4,%5,%6,%7},{%8,%9},{%0,%1,%2,%3};"
        : "+f"(c[0]), "+f"(c[1]), "+f"(c[2]), "+f"(c[3])
        : "r"(a0), "r"(a1), "r"(a2), "r"(a3), "r"(b0), "r"(b1));
}

// ---------------- generic helpers ----------------
__device__ __forceinline__ float blockReduceB(float v, volatile float* sred) {
    int lane = threadIdx.x & 31;
    int wid = threadIdx.x >> 5;
    #pragma unroll
    for (int o = 16; o > 0; o >>= 1) v += __shfl_down_sync(0xffffffffu, v, o);
    if (lane == 0) sred[wid] = v;
    __syncthreads();
    if (threadIdx.x < 32) {
        int nw = (blockDim.x + 31) >> 5;
        float x = (threadIdx.x < nw) ? sred[threadIdx.x] : 0.0f;
        #pragma unroll
        for (int o = 16; o > 0; o >>= 1) x += __shfl_down_sync(0xffffffffu, x, o);
        if (threadIdx.x == 0) sred[0] = x;
    }
    __syncthreads();
    float r = sred[0];
    __syncthreads();
    return r;
}

// ---------------- norms over D for (b, m), layout (B, D, len) ----------------
__global__ void norms_kernel(const float* __restrict__ E, float* __restrict__ out) {
    int idx = blockIdx.x * blockDim.x + threadIdx.x;
    int b = idx >> 10;
    int m = idx & 1023;
    const float* p = E + (size_t)b * DIMD * MSZ + m;
    float s = 0.0f;
    #pragma unroll 8
    for (int d = 0; d < DIMD; d++) {
        float x = p[(size_t)d * MSZ];
        s += x * x;
    }
    out[idx] = sqrtf(s);
}

// ---------------- TF32 mma.sync GEMM + exp epilogue ----------------
// Staging: LDG -> cvt.rna.tf32 -> STS (register double-buffer).
// Mainloop is pure LDS + MMA (no ALU cvt on the critical path).
// MMA operand bits identical to the cp.async+cvt version -> same numerics.
#define KC 16
#define SSTR 136
__global__ void __launch_bounds__(256, 2) gemm_mma_kernel(
        const float* __restrict__ Ae, const float* __restrict__ Be,
        const float* __restrict__ lptr) {
    __shared__ uint32_t sA[2][KC][SSTR];
    __shared__ uint32_t sB[2][KC][SSTR];

    int b = blockIdx.z;
    int m0 = blockIdx.y * 128;
    int n0 = blockIdx.x * 128;
    int tid = threadIdx.x;
    int wid = tid >> 5;
    int lane = tid & 31;
    int g = lane >> 2;
    int tig = lane & 3;
    int warp_m = (wid >> 2) * 64;
    int warp_n = (wid & 3) * 32;

    const float* Ab = Ae + (size_t)b * DIMD * MSZ;
    const float* Bb = Be + (size_t)b * DIMD * NSZ;

    // per-thread staging slots: slot = tid + i*256, i in {0,1}
    int kr0 = tid >> 5;              // slot0 row
    int c40 = tid & 31;
    int kr1 = (tid + 256) >> 5;      // slot1 row
    int c41 = c40;                   // (tid+256)&31 == tid&31

    float acc[4][4][4];
    #pragma unroll
    for (int mi = 0; mi < 4; mi++)
        #pragma unroll
        for (int ni = 0; ni < 4; ni++)
            #pragma unroll
            for (int q = 0; q < 4; q++) acc[mi][ni][q] = 0.0f;

    float4 ra0, ra1, rb0, rb1;

    // prologue: LDG chunk 0
    ra0 = *(const float4*)&Ab[(size_t)kr0 * MSZ + m0 + c40 * 4];
    ra1 = *(const float4*)&Ab[(size_t)kr1 * MSZ + m0 + c41 * 4];
    rb0 = *(const float4*)&Bb[(size_t)kr0 * NSZ + n0 + c40 * 4];
    rb1 = *(const float4*)&Bb[(size_t)kr1 * NSZ + n0 + c41 * 4];
    {
        uint32_t* pa0 = &sA[0][kr0][c40 * 4];
        uint32_t* pa1 = &sA[0][kr1][c41 * 4];
        uint32_t* pb0 = &sB[0][kr0][c40 * 4];
        uint32_t* pb1 = &sB[0][kr1][c41 * 4];
        pa0[0] = f2tf(ra0.x); pa0[1] = f2tf(ra0.y); pa0[2] = f2tf(ra0.z); pa0[3] = f2tf(ra0.w);
        pa1[0] = f2tf(ra1.x); pa1[1] = f2tf(ra1.y); pa1[2] = f2tf(ra1.z); pa1[3] = f2tf(ra1.w);
        pb0[0] = f2tf(rb0.x); pb0[1] = f2tf(rb0.y); pb0[2] = f2tf(rb0.z); pb0[3] = f2tf(rb0.w);
        pb1[0] = f2tf(rb1.x); pb1[1] = f2tf(rb1.y); pb1[2] = f2tf(rb1.z); pb1[3] = f2tf(rb1.w);
    }
    __syncthreads();

    const int NCH = DIMD / KC;   // 32
    for (int c = 0; c < NCH; c++) {
        // issue LDG for chunk c+1 early (latency hidden under MMAs)
        if (c + 1 < NCH) {
            int kb = (c + 1) * KC;
            ra0 = *(const float4*)&Ab[(size_t)(kb + kr0) * MSZ + m0 + c40 * 4];
            ra1 = *(const float4*)&Ab[(size_t)(kb + kr1) * MSZ + m0 + c41 * 4];
            rb0 = *(const float4*)&Bb[(size_t)(kb + kr0) * NSZ + n0 + c40 * 4];
            rb1 = *(const float4*)&Bb[(size_t)(kb + kr1) * NSZ + n0 + c41 * 4];
        }

        int cb = c & 1;
        #pragma unroll
        for (int ks = 0; ks < 2; ks++) {
            int k0 = ks * 8;
            uint32_t bf[4][2];
            #pragma unroll
            for (int ni = 0; ni < 4; ni++) {
                int nn = warp_n + ni * 8 + g;
                bf[ni][0] = sB[cb][k0 + tig][nn];
                bf[ni][1] = sB[cb][k0 + tig + 4][nn];
            }
            #pragma unroll
            for (int mi = 0; mi < 4; mi++) {
                int mm = warp_m + mi * 16 + g;
                uint32_t a0 = sA[cb][k0 + tig][mm];
                uint32_t a1 = sA[cb][k0 + tig][mm + 8];
                uint32_t a2 = sA[cb][k0 + tig + 4][mm];
                uint32_t a3 = sA[cb][k0 + tig + 4][mm + 8];
                #pragma unroll
                for (int ni = 0; ni < 4; ni++)
                    mma_tf32(acc[mi][ni], a0, a1, a2, a3, bf[ni][0], bf[ni][1]);
            }
        }

        if (c + 1 < NCH) {
            int nb = (c + 1) & 1;
            uint32_t* pa0 = &sA[nb][kr0][c40 * 4];
            uint32_t* pa1 = &sA[nb][kr1][c41 * 4];
            uint32_t* pb0 = &sB[nb][kr0][c40 * 4];
            uint32_t* pb1 = &sB[nb][kr1][c41 * 4];
            pa0[0] = f2tf(ra0.x); pa0[1] = f2tf(ra0.y); pa0[2] = f2tf(ra0.z); pa0[3] = f2tf(ra0.w);
            pa1[0] = f2tf(ra1.x); pa1[1] = f2tf(ra1.y); pa1[2] = f2tf(ra1.z); pa1[3] = f2tf(ra1.w);
            pb0[0] = f2tf(rb0.x); pb0[1] = f2tf(rb0.y); pb0[2] = f2tf(rb0.z); pb0[3] = f2tf(rb0.w);
            pb1[0] = f2tf(rb1.x); pb1[1] = f2tf(rb1.y); pb1[2] = f2tf(rb1.z); pb1[3] = f2tf(rb1.w);
        }
        __syncthreads();
    }

    float linv = 1.0f / fmaxf(lptr[0], 1e-8f);
    float n2r[8];
    #pragma unroll
    for (int ni = 0; ni < 4; ni++) {
        int nc = n0 + warp_n + ni * 8 + 2 * tig;
        n2r[ni * 2]     = g_n2[b * NSZ + nc];
        n2r[ni * 2 + 1] = g_n2[b * NSZ + nc + 1];
    }
    #pragma unroll
    for (int mi = 0; mi < 4; mi++) {
        #pragma unroll
        for (int half = 0; half < 2; half++) {
            int m = m0 + warp_m + mi * 16 + g + half * 8;
            float n1v = g_n1[b * MSZ + m];
            float* Krow = g_K + ((size_t)(b * MSZ + m)) * NSZ + n0 + warp_n;
            #pragma unroll
            for (int ni = 0; ni < 4; ni++) {
                float x0 = acc[mi][ni][half * 2 + 0];
                float x1 = acc[mi][ni][half * 2 + 1];
                float d0 = fmaxf(n1v * n2r[ni * 2], 1e-6f);
                float d1 = fmaxf(n1v * n2r[ni * 2 + 1], 1e-6f);
                float o0 = expf(-(1.0f - x0 / d0) * linv);
                float o1 = expf(-(1.0f - x1 / d1) * linv);
                *(float2*)&Krow[ni * 8 + 2 * tig] = make_float2(o0, o1);
            }
        }
    }
}

// ---------------- init u,v ----------------
__global__ void init_uv_kernel() {
    int idx = blockIdx.x * blockDim.x + threadIdx.x;
    if (idx < BATCH * MSZ) g_u[idx] = 1.0f / (float)MSZ;
    if (idx < BATCH * NSZ) g_v[idx] = 1.0f / (float)NSZ;
}

// ---------------- fused Sinkhorn iteration (round-4 version: measured best) ---
__global__ void __launch_bounds__(256) sink_fused_kernel(
        const float* __restrict__ lptr, const float* __restrict__ rptr) {
    __shared__ float su[32];
    int b = blockIdx.y;
    int m0 = blockIdx.x * 32;
    int tid = threadIdx.x;
    int wid = tid >> 5;
    int lane = tid & 31;

    float lv = lptr[0], rv = rptr[0];
    float fi = rv / fmaxf(rv + lv, 1e-8f);
    float a = 1.0f / (float)MSZ;

    const float4* v4 = (const float4*)(g_v + b * NSZ);

    #pragma unroll
    for (int rr = 0; rr < 4; rr++) {
        int r = (wid << 2) | rr;
        const float4* Kr = (const float4*)(g_K + ((size_t)(b * MSZ + m0 + r)) * NSZ);
        float s = 0.0f;
        #pragma unroll
        for (int j = 0; j < 8; j++) {
            float4 kk = Kr[j * 32 + lane];
            float4 vv = v4[j * 32 + lane];
            s += kk.x * vv.x + kk.y * vv.y + kk.z * vv.z + kk.w * vv.w;
        }
        #pragma unroll
        for (int o = 16; o > 0; o >>= 1) s += __shfl_down_sync(0xffffffffu, s, o);
        if (lane == 0) {
            float uu = powf(a / fmaxf(s, 1e-8f), fi);
            g_u[b * MSZ + m0 + r] = uu;
            su[r] = uu;
        }
    }
    __syncthreads();

    const float* Kb = g_K + (size_t)(b * MSZ + m0) * NSZ;
    float4 acc = make_float4(0.f, 0.f, 0.f, 0.f);
    #pragma unroll 4
    for (int r = 0; r < 32; r++) {
        float uu = su[r];
        float4 kk = *(const float4*)&Kb[(size_t)r * NSZ + tid * 4];
        acc.x += uu * kk.x;
        acc.y += uu * kk.y;
        acc.z += uu * kk.z;
        acc.w += uu * kk.w;
    }
    *(float4*)&g_vpart[((size_t)blockIdx.x * BATCH + b) * NSZ + tid * 4] = acc;
}

// ---------------- v = (b / clip(colsum, eps))^fi ----------------
__global__ void sink_vpow_kernel(const float* __restrict__ lptr, const float* __restrict__ rptr) {
    int idx = blockIdx.x * blockDim.x + threadIdx.x;
    int b = idx >> 10;
    int n = idx & 1023;
    float s = 0.0f;
    #pragma unroll
    for (int z = 0; z < MSPLIT; z++)
        s += g_vpart[((size_t)z * BATCH + b) * NSZ + n];
    float lv = lptr[0], rv = rptr[0];
    float fi = rv / fmaxf(rv + lv, 1e-8f);
    float bb = 1.0f / (float)NSZ;
    g_v[idx] = powf(bb / fmaxf(s, 1e-8f), fi);
}

// ---------------- P = u*K*v, row sums, weighted_ref (one pass over K) ---------
__global__ void compute_P_kernel(const float* __restrict__ tgt, float* __restrict__ Pout) {
    __shared__ float sred[32];
    int bm = blockIdx.x;
    int b = bm >> 10;
    float uu = g_u[bm];
    const float4* Krow = (const float4*)(g_K + (size_t)bm * NSZ);
    const float4* vrow = (const float4*)(g_v + b * NSZ);
    float4* Prow = (float4*)(Pout + (size_t)bm * NSZ);
    const float4* t0 = (const float4*)(tgt + ((size_t)b * 3 + 0) * NSZ);
    const float4* t1 = (const float4*)(tgt + ((size_t)b * 3 + 1) * NSZ);
    const float4* t2 = (const float4*)(tgt + ((size_t)b * 3 + 2) * NSZ);

    int t = threadIdx.x;
    float4 kk = Krow[t];
    float4 vv = vrow[t];
    float4 p;
    p.x = uu * kk.x * vv.x;
    p.y = uu * kk.y * vv.y;
    p.z = uu * kk.z * vv.z;
    p.w = uu * kk.w * vv.w;
    Prow[t] = p;

    float4 a0 = t0[t], a1 = t1[t], a2 = t2[t];
    float rs = p.x + p.y + p.z + p.w;
    float w0 = p.x * a0.x + p.y * a0.y + p.z * a0.z + p.w * a0.w;
    float w1 = p.x * a1.x + p.y * a1.y + p.z * a1.z + p.w * a1.w;
    float w2 = p.x * a2.x + p.y * a2.y + p.z * a2.z + p.w * a2.w;

    rs = blockReduceB(rs, sred);
    w0 = blockReduceB(w0, sred);
    w1 = blockReduceB(w1, sred);
    w2 = blockReduceB(w2, sred);
    if (threadIdx.x == 0) {
        g_rowS[bm] = rs;
        float inv = 1.0f / (rs + 1e-6f);
        g_wref[bm * 3 + 0] = w0 * inv;
        g_wref[bm * 3 + 1] = w1 * inv;
        g_wref[bm * 3 + 2] = w2 * inv;
    }
}

// ---------------- per-batch centroids + covariance ----------------
__global__ void cov_kernel(const float* __restrict__ src) {
    __shared__ float sred[32];
    int b = blockIdx.x;
    int t = threadIdx.x;

    float s = 0.0f;
    for (int m = t; m < MSZ; m += 256) s += g_rowS[b * MSZ + m];
    float S = blockReduceB(s, sred);
    float inv = 1.0f / (S + 1e-6f);

    float ca[3] = {0, 0, 0}, cb[3] = {0, 0, 0};
    for (int m = t; m < MSZ; m += 256) {
        float w = g_rowS[b * MSZ + m] * inv;
        #pragma unroll
        for (int d = 0; d < 3; d++) {
            ca[d] += w * src[((size_t)b * 3 + d) * MSZ + m];
            cb[d] += w * g_wref[(b * MSZ + m) * 3 + d];
        }
    }
    float CA[3], CB[3];
    #pragma unroll
    for (int d = 0; d < 3; d++) CA[d] = blockReduceB(ca[d], sred);
    #pragma unroll
    for (int d = 0; d < 3; d++) CB[d] = blockReduceB(cb[d], sred);

    float cv[9] = {0, 0, 0, 0, 0, 0, 0, 0, 0};
    for (int m = t; m < MSZ; m += 256) {
        float w = g_rowS[b * MSZ + m] * inv;
        float ac[3], bc[3];
        #pragma unroll
        for (int d = 0; d < 3; d++) {
            ac[d] = src[((size_t)b * 3 + d) * MSZ + m] - CA[d];
            bc[d] = g_wref[(b * MSZ + m) * 3 + d] - CB[d];
        }
        #pragma unroll
        for (int i = 0; i < 3; i++)
            #pragma unroll
            for (int j = 0; j < 3; j++)
                cv[i * 3 + j] += ac[i] * bc[j] * w;
    }
    #pragma unroll
    for (int k = 0; k < 9; k++) {
        float r = blockReduceB(cv[k], sred);
        if (t == 0) g_cov[b * 9 + k] = r;
    }
    if (t == 0) {
        #pragma unroll
        for (int d = 0; d < 3; d++) { g_ca[b * 3 + d] = CA[d]; g_cb[b * 3 + d] = CB[d]; }
    }
}

// ---------------- 3x3 SVD (fp64 Jacobi) + Kabsch R,t ----------------
__global__ void svd_kernel(float* __restrict__ out) {
    int b = threadIdx.x;
    if (b >= BATCH) return;

    double A[3][3];
    #pragma unroll
    for (int i = 0; i < 3; i++)
        #pragma unroll
        for (int j = 0; j < 3; j++)
            A[i][j] = (double)g_cov[b * 9 + i * 3 + j];

    double S[3][3];
    #pragma unroll
    for (int i = 0; i < 3; i++)
        #pragma unroll
        for (int j = 0; j < 3; j++) {
            double acc = 0.0;
            #pragma unroll
            for (int k = 0; k < 3; k++) acc += A[k][i] * A[k][j];
            S[i][j] = acc;
        }

    double V[3][3] = {{1, 0, 0}, {0, 1, 0}, {0, 0, 1}};
    const int PP[3] = {0, 0, 1};
    const int QQ[3] = {1, 2, 2};
    for (int sweep = 0; sweep < 20; sweep++) {
        for (int r = 0; r < 3; r++) {
            int p = PP[r], q = QQ[r];
            double apq = S[p][q];
            if (apq == 0.0) continue;
            double theta = (S[q][q] - S[p][p]) / (2.0 * apq);
            double tt = copysign(1.0, theta) / (fabs(theta) + sqrt(1.0 + theta * theta));
            double c = 1.0 / sqrt(1.0 + tt * tt);
            double sn = tt * c;
            for (int k = 0; k < 3; k++) {
                double skp = S[k][p], skq = S[k][q];
                S[k][p] = c * skp - sn * skq;
                S[k][q] = sn * skp + c * skq;
            }
            for (int k = 0; k < 3; k++) {
                double spk = S[p][k], sqk = S[q][k];
                S[p][k] = c * spk - sn * sqk;
                S[q][k] = sn * spk + c * sqk;
            }
            for (int k = 0; k < 3; k++) {
                double vkp = V[k][p], vkq = V[k][q];
                V[k][p] = c * vkp - sn * vkq;
                V[k][q] = sn * vkp + c * vkq;
            }
        }
    }

    double ev[3] = {S[0][0], S[1][1], S[2][2]};
    int idx[3] = {0, 1, 2};
    for (int i = 0; i < 2; i++)
        for (int j = i + 1; j < 3; j++)
            if (ev[idx[j]] > ev[idx[i]]) { int tmp = idx[i]; idx[i] = idx[j]; idx[j] = tmp; }

    double Vs[3][3];
    #pragma unroll
    for (int k = 0; k < 3; k++)
        for (int i = 0; i < 3; i++)
            Vs[k][i] = V[k][idx[i]];

    double U[3][3];
    double nrm[3];
    for (int i = 0; i < 3; i++) {
        double u0 = A[0][0] * Vs[0][i] + A[0][1] * Vs[1][i] + A[0][2] * Vs[2][i];
        double u1 = A[1][0] * Vs[0][i] + A[1][1] * Vs[1][i] + A[1][2] * Vs[2][i];
        double u2 = A[2][0] * Vs[0][i] + A[2][1] * Vs[1][i] + A[2][2] * Vs[2][i];
        double nm = sqrt(u0 * u0 + u1 * u1 + u2 * u2);
        nrm[i] = nm;
        double in = (nm > 1e-300) ? 1.0 / nm : 0.0;
        U[0][i] = u0 * in; U[1][i] = u1 * in; U[2][i] = u2 * in;
    }
    if (nrm[2] < 1e-12 * fmax(nrm[0], 1e-300)) {
        U[0][2] = U[1][0] * U[2][1] - U[2][0] * U[1][1];
        U[1][2] = U[2][0] * U[0][1] - U[0][0] * U[2][1];
        U[2][2] = U[0][0] * U[1][1] - U[1][0] * U[0][1];
    }

    double R[3][3];
    for (int i = 0; i < 3; i++)
        for (int j = 0; j < 3; j++)
            R[i][j] = Vs[i][0] * U[j][0] + Vs[i][1] * U[j][1] + Vs[i][2] * U[j][2];

    double det = R[0][0] * (R[1][1] * R[2][2] - R[1][2] * R[2][1])
               - R[0][1] * (R[1][0] * R[2][2] - R[1][2] * R[2][0])
               + R[0][2] * (R[1][0] * R[2][1] - R[1][1] * R[2][0]);
    if (!(det > 0.0)) {
        for (int i = 0; i < 3; i++)
            for (int j = 0; j < 3; j++)
                R[i][j] -= 2.0 * Vs[i][2] * U[j][2];
    }

    double ca[3] = {(double)g_ca[b * 3], (double)g_ca[b * 3 + 1], (double)g_ca[b * 3 + 2]};
    double cb[3] = {(double)g_cb[b * 3], (double)g_cb[b * 3 + 1], (double)g_cb[b * 3 + 2]};
    double tv[3];
    for (int i = 0; i < 3; i++)
        tv[i] = -(R[i][0] * ca[0] + R[i][1] * ca[1] + R[i][2] * ca[2]) + cb[i];

    for (int i = 0; i < 3; i++)
        for (int j = 0; j < 3; j++)
            out[b * 9 + i * 3 + j] = (float)R[i][j];
    for (int i = 0; i < 3; i++)
        out[288 + b * 3 + i] = (float)tv[i];
}

// ---------------- launch ----------------
extern "C" void kernel_launch(void* const* d_in, const int* in_sizes, int n_in,
                              void* d_out, int out_size) {
    const float* src_emb = (const float*)d_in[0];
    const float* tgt_emb = (const float*)d_in[1];
    const float* src     = (const float*)d_in[2];
    const float* tgt     = (const float*)d_in[3];
    const float* lptr    = (const float*)d_in[4];
    const float* rptr    = (const float*)d_in[5];
    float* out = (float*)d_out;
    float* Pout = out + BATCH * 9 + BATCH * 3;

    float* dn1; cudaGetSymbolAddress((void**)&dn1, g_n1);
    float* dn2; cudaGetSymbolAddress((void**)&dn2, g_n2);

    // launch order keeps gemm_mma_kernel as the 4th launch (ncu sample slot)
    init_uv_kernel<<<(BATCH * MSZ) / 256, 256>>>();
    norms_kernel<<<(BATCH * MSZ) / 256, 256>>>(src_emb, dn1);
    norms_kernel<<<(BATCH * NSZ) / 256, 256>>>(tgt_emb, dn2);

    dim3 ggrid(NSZ / 128, MSZ / 128, BATCH);
    gemm_mma_kernel<<<ggrid, 256>>>(src_emb, tgt_emb, lptr);

    for (int it = 0; it < SINK_ITERS; it++) {
        dim3 sgrid(MSZ / 32, BATCH);
        sink_fused_kernel<<<sgrid, 256>>>(lptr, rptr);
        sink_vpow_kernel<<<(BATCH * NSZ) / 256, 256>>>(lptr, rptr);
    }

    compute_P_kernel<<<BATCH * MSZ, 256>>>(tgt, Pout);
    cov_kernel<<<BATCH, 256>>>(src);
    svd_kernel<<<1, 32>>>(out);
}

// round 8
// speedup vs baseline: 1.1778x; 1.0660x over previous
#include <cuda_runtime.h>
#include <math.h>
#include <stdint.h>

#define BATCH 32
#define DIMD  512
#define MSZ   1024
#define NSZ   1024
#define SINK_ITERS 5
#define MSPLIT 32

// ---------------- device scratch (static: no allocations) ----------------
__device__ float    g_K [(size_t)BATCH * MSZ * NSZ];   // 134 MB fp32 kernel matrix
__device__ uint16_t g_Kh[(size_t)BATCH * MSZ * NSZ];   //  67 MB bf16 shadow (Sinkhorn reads)
__device__ float g_n1[BATCH * MSZ];
__device__ float g_n2[BATCH * NSZ];
__device__ float g_u[BATCH * MSZ];
__device__ float g_v[BATCH * NSZ];
__device__ float g_vpart[(size_t)MSPLIT * BATCH * NSZ];
__device__ float g_rowS[BATCH * MSZ];
__device__ float g_wref[BATCH * MSZ * 3];
__device__ float g_cov[BATCH * 9];
__device__ float g_ca[BATCH * 3];
__device__ float g_cb[BATCH * 3];

// ---------------- PTX helpers ----------------
__device__ __forceinline__ uint32_t f2tf(float x) {
    uint32_t r;
    asm("cvt.rna.tf32.f32 %0, %1;" : "=r"(r) : "f"(x));
    return r;
}
__device__ __forceinline__ uint32_t pack_bf16x2(float lo, float hi) {
    uint32_t r;
    asm("cvt.rn.bf16x2.f32 %0, %1, %2;" : "=r"(r) : "f"(hi), "f"(lo));
    return r;
}
// exact bf16 -> fp32 (value << 16)
__device__ __forceinline__ float bf_lo(uint32_t u) { return __uint_as_float(u << 16); }
__device__ __forceinline__ float bf_hi(uint32_t u) { return __uint_as_float(u & 0xFFFF0000u); }

__device__ __forceinline__ void mma_tf32(float* c, uint32_t a0, uint32_t a1,
                                         uint32_t a2, uint32_t a3,
                                         uint32_t b0, uint32_t b1) {
    asm volatile(
        "mma.sync.aligned.m16n8k8.row.col.f32.tf32.tf32.f32 "
        "{%0,%1,%2,%3},{%4,%5,%6,%7},{%8,%9},{%0,%1,%2,%3};"
        : "+f"(c[0]), "+f"(c[1]), "+f"(c[2]), "+f"(c[3])
        : "r"(a0), "r"(a1), "r"(a2), "r"(a3), "r"(b0), "r"(b1));
}

// ---------------- generic helpers ----------------
__device__ __forceinline__ float blockReduceB(float v, volatile float* sred) {
    int lane = threadIdx.x & 31;
    int wid = threadIdx.x >> 5;
    #pragma unroll
    for (int o = 16; o > 0; o >>= 1) v += __shfl_down_sync(0xffffffffu, v, o);
    if (lane == 0) sred[wid] = v;
    __syncthreads();
    if (threadIdx.x < 32) {
        int nw = (blockDim.x + 31) >> 5;
        float x = (threadIdx.x < nw) ? sred[threadIdx.x] : 0.0f;
        #pragma unroll
        for (int o = 16; o > 0; o >>= 1) x += __shfl_down_sync(0xffffffffu, x, o);
        if (threadIdx.x == 0) sred[0] = x;
    }
    __syncthreads();
    float r = sred[0];
    __syncthreads();
    return r;
}

// ---------------- norms over D for (b, m), layout (B, D, len) ----------------
__global__ void norms_kernel(const float* __restrict__ E, float* __restrict__ out) {
    int idx = blockIdx.x * blockDim.x + threadIdx.x;
    int b = idx >> 10;
    int m = idx & 1023;
    const float* p = E + (size_t)b * DIMD * MSZ + m;
    float s = 0.0f;
    #pragma unroll 8
    for (int d = 0; d < DIMD; d++) {
        float x = p[(size_t)d * MSZ];
        s += x * x;
    }
    out[idx] = sqrtf(s);
}

// ---------------- TF32 mma.sync GEMM + exp epilogue (mainloop unchanged) ------
#define KC 16
#define SSTR 136
__global__ void __launch_bounds__(256, 2) gemm_mma_kernel(
        const float* __restrict__ Ae, const float* __restrict__ Be,
        const float* __restrict__ lptr) {
    __shared__ uint32_t sA[2][KC][SSTR];
    __shared__ uint32_t sB[2][KC][SSTR];

    int b = blockIdx.z;
    int m0 = blockIdx.y * 128;
    int n0 = blockIdx.x * 128;
    int tid = threadIdx.x;
    int wid = tid >> 5;
    int lane = tid & 31;
    int g = lane >> 2;
    int tig = lane & 3;
    int warp_m = (wid >> 2) * 64;
    int warp_n = (wid & 3) * 32;

    const float* Ab = Ae + (size_t)b * DIMD * MSZ;
    const float* Bb = Be + (size_t)b * DIMD * NSZ;

    int kr0 = tid >> 5;
    int c40 = tid & 31;
    int kr1 = (tid + 256) >> 5;
    int c41 = c40;

    float acc[4][4][4];
    #pragma unroll
    for (int mi = 0; mi < 4; mi++)
        #pragma unroll
        for (int ni = 0; ni < 4; ni++)
            #pragma unroll
            for (int q = 0; q < 4; q++) acc[mi][ni][q] = 0.0f;

    float4 ra0, ra1, rb0, rb1;

    ra0 = *(const float4*)&Ab[(size_t)kr0 * MSZ + m0 + c40 * 4];
    ra1 = *(const float4*)&Ab[(size_t)kr1 * MSZ + m0 + c41 * 4];
    rb0 = *(const float4*)&Bb[(size_t)kr0 * NSZ + n0 + c40 * 4];
    rb1 = *(const float4*)&Bb[(size_t)kr1 * NSZ + n0 + c41 * 4];
    {
        uint32_t* pa0 = &sA[0][kr0][c40 * 4];
        uint32_t* pa1 = &sA[0][kr1][c41 * 4];
        uint32_t* pb0 = &sB[0][kr0][c40 * 4];
        uint32_t* pb1 = &sB[0][kr1][c41 * 4];
        pa0[0] = f2tf(ra0.x); pa0[1] = f2tf(ra0.y); pa0[2] = f2tf(ra0.z); pa0[3] = f2tf(ra0.w);
        pa1[0] = f2tf(ra1.x); pa1[1] = f2tf(ra1.y); pa1[2] = f2tf(ra1.z); pa1[3] = f2tf(ra1.w);
        pb0[0] = f2tf(rb0.x); pb0[1] = f2tf(rb0.y); pb0[2] = f2tf(rb0.z); pb0[3] = f2tf(rb0.w);
        pb1[0] = f2tf(rb1.x); pb1[1] = f2tf(rb1.y); pb1[2] = f2tf(rb1.z); pb1[3] = f2tf(rb1.w);
    }
    __syncthreads();

    const int NCH = DIMD / KC;
    for (int c = 0; c < NCH; c++) {
        if (c + 1 < NCH) {
            int kb = (c + 1) * KC;
            ra0 = *(const float4*)&Ab[(size_t)(kb + kr0) * MSZ + m0 + c40 * 4];
            ra1 = *(const float4*)&Ab[(size_t)(kb + kr1) * MSZ + m0 + c41 * 4];
            rb0 = *(const float4*)&Bb[(size_t)(kb + kr0) * NSZ + n0 + c40 * 4];
            rb1 = *(const float4*)&Bb[(size_t)(kb + kr1) * NSZ + n0 + c41 * 4];
        }

        int cb = c & 1;
        #pragma unroll
        for (int ks = 0; ks < 2; ks++) {
            int k0 = ks * 8;
            uint32_t bf[4][2];
            #pragma unroll
            for (int ni = 0; ni < 4; ni++) {
                int nn = warp_n + ni * 8 + g;
                bf[ni][0] = sB[cb][k0 + tig][nn];
                bf[ni][1] = sB[cb][k0 + tig + 4][nn];
            }
            #pragma unroll
            for (int mi = 0; mi < 4; mi++) {
                int mm = warp_m + mi * 16 + g;
                uint32_t a0 = sA[cb][k0 + tig][mm];
                uint32_t a1 = sA[cb][k0 + tig][mm + 8];
                uint32_t a2 = sA[cb][k0 + tig + 4][mm];
                uint32_t a3 = sA[cb][k0 + tig + 4][mm + 8];
                #pragma unroll
                for (int ni = 0; ni < 4; ni++)
                    mma_tf32(acc[mi][ni], a0, a1, a2, a3, bf[ni][0], bf[ni][1]);
            }
        }

        if (c + 1 < NCH) {
            int nb = (c + 1) & 1;
            uint32_t* pa0 = &sA[nb][kr0][c40 * 4];
            uint32_t* pa1 = &sA[nb][kr1][c41 * 4];
            uint32_t* pb0 = &sB[nb][kr0][c40 * 4];
            uint32_t* pb1 = &sB[nb][kr1][c41 * 4];
            pa0[0] = f2tf(ra0.x); pa0[1] = f2tf(ra0.y); pa0[2] = f2tf(ra0.z); pa0[3] = f2tf(ra0.w);
            pa1[0] = f2tf(ra1.x); pa1[1] = f2tf(ra1.y); pa1[2] = f2tf(ra1.z); pa1[3] = f2tf(ra1.w);
            pb0[0] = f2tf(rb0.x); pb0[1] = f2tf(rb0.y); pb0[2] = f2tf(rb0.z); pb0[3] = f2tf(rb0.w);
            pb1[0] = f2tf(rb1.x); pb1[1] = f2tf(rb1.y); pb1[2] = f2tf(rb1.z); pb1[3] = f2tf(rb1.w);
        }
        __syncthreads();
    }

    // epilogue: cosine + exp, write fp32 K and bf16 shadow
    float linv = 1.0f / fmaxf(lptr[0], 1e-8f);
    float n2r[8];
    #pragma unroll
    for (int ni = 0; ni < 4; ni++) {
        int nc = n0 + warp_n + ni * 8 + 2 * tig;
        n2r[ni * 2]     = g_n2[b * NSZ + nc];
        n2r[ni * 2 + 1] = g_n2[b * NSZ + nc + 1];
    }
    #pragma unroll
    for (int mi = 0; mi < 4; mi++) {
        #pragma unroll
        for (int half = 0; half < 2; half++) {
            int m = m0 + warp_m + mi * 16 + g + half * 8;
            float n1v = g_n1[b * MSZ + m];
            size_t rowoff = ((size_t)(b * MSZ + m)) * NSZ + n0 + warp_n;
            float* Krow = g_K + rowoff;
            uint32_t* Khrow = (uint32_t*)(g_Kh + rowoff);
            #pragma unroll
            for (int ni = 0; ni < 4; ni++) {
                float x0 = acc[mi][ni][half * 2 + 0];
                float x1 = acc[mi][ni][half * 2 + 1];
                float d0 = fmaxf(n1v * n2r[ni * 2], 1e-6f);
                float d1 = fmaxf(n1v * n2r[ni * 2 + 1], 1e-6f);
                float o0 = expf(-(1.0f - x0 / d0) * linv);
                float o1 = expf(-(1.0f - x1 / d1) * linv);
                *(float2*)&Krow[ni * 8 + 2 * tig] = make_float2(o0, o1);
                Khrow[ni * 4 + tig] = pack_bf16x2(o0, o1);
            }
        }
    }
}

// ---------------- init u,v ----------------
__global__ void init_uv_kernel() {
    int idx = blockIdx.x * blockDim.x + threadIdx.x;
    if (idx < BATCH * MSZ) g_u[idx] = 1.0f / (float)MSZ;
    if (idx < BATCH * NSZ) g_v[idx] = 1.0f / (float)NSZ;
}

// ---------------- fused Sinkhorn iteration over bf16 K shadow ----------------
__global__ void __launch_bounds__(256) sink_fused_kernel(
        const float* __restrict__ lptr, const float* __restrict__ rptr) {
    __shared__ float su[32];
    int b = blockIdx.y;
    int m0 = blockIdx.x * 32;
    int tid = threadIdx.x;
    int wid = tid >> 5;
    int lane = tid & 31;

    float lv = lptr[0], rv = rptr[0];
    float fi = rv / fmaxf(rv + lv, 1e-8f);
    float a = 1.0f / (float)MSZ;

    const float4* v4 = (const float4*)(g_v + b * NSZ);

    // Phase A: warp w handles rows 4w..4w+3; 4 x uint4 (8 bf16) per lane per row
    #pragma unroll
    for (int rr = 0; rr < 4; rr++) {
        int r = (wid << 2) | rr;
        const uint4* Kr = (const uint4*)(g_Kh + ((size_t)(b * MSZ + m0 + r)) * NSZ);
        float s = 0.0f;
        #pragma unroll
        for (int j = 0; j < 4; j++) {
            int sl = j * 32 + lane;          // 0..127 uint4 slots
            uint4 kk = Kr[sl];
            float4 va = v4[sl * 2];
            float4 vb = v4[sl * 2 + 1];
            s += bf_lo(kk.x) * va.x + bf_hi(kk.x) * va.y
               + bf_lo(kk.y) * va.z + bf_hi(kk.y) * va.w
               + bf_lo(kk.z) * vb.x + bf_hi(kk.z) * vb.y
               + bf_lo(kk.w) * vb.z + bf_hi(kk.w) * vb.w;
        }
        #pragma unroll
        for (int o = 16; o > 0; o >>= 1) s += __shfl_down_sync(0xffffffffu, s, o);
        if (lane == 0) {
            float uu = powf(a / fmaxf(s, 1e-8f), fi);
            g_u[b * MSZ + m0 + r] = uu;
            su[r] = uu;
        }
    }
    __syncthreads();

    // Phase B: thread owns 4 columns (uint2 = 4 bf16), accumulate over 32 rows
    const uint16_t* Kbh = g_Kh + (size_t)(b * MSZ + m0) * NSZ;
    float4 acc = make_float4(0.f, 0.f, 0.f, 0.f);
    #pragma unroll 4
    for (int r = 0; r < 32; r++) {
        float uu = su[r];
        uint2 kk = *(const uint2*)&Kbh[(size_t)r * NSZ + tid * 4];
        acc.x += uu * bf_lo(kk.x);
        acc.y += uu * bf_hi(kk.x);
        acc.z += uu * bf_lo(kk.y);
        acc.w += uu * bf_hi(kk.y);
    }
    *(float4*)&g_vpart[((size_t)blockIdx.x * BATCH + b) * NSZ + tid * 4] = acc;
}

// ---------------- v = (b / clip(colsum, eps))^fi ----------------
__global__ void sink_vpow_kernel(const float* __restrict__ lptr, const float* __restrict__ rptr) {
    int idx = blockIdx.x * blockDim.x + threadIdx.x;
    int b = idx >> 10;
    int n = idx & 1023;
    float s = 0.0f;
    #pragma unroll
    for (int z = 0; z < MSPLIT; z++)
        s += g_vpart[((size_t)z * BATCH + b) * NSZ + n];
    float lv = lptr[0], rv = rptr[0];
    float fi = rv / fmaxf(rv + lv, 1e-8f);
    float bb = 1.0f / (float)NSZ;
    g_v[idx] = powf(bb / fmaxf(s, 1e-8f), fi);
}

// ---------------- P = u*K*v, row sums, weighted_ref (fp32 K, one pass) -------
__global__ void compute_P_kernel(const float* __restrict__ tgt, float* __restrict__ Pout) {
    __shared__ float sred[32];
    int bm = blockIdx.x;
    int b = bm >> 10;
    float uu = g_u[bm];
    const float4* Krow = (const float4*)(g_K + (size_t)bm * NSZ);
    const float4* vrow = (const float4*)(g_v + b * NSZ);
    float4* Prow = (float4*)(Pout + (size_t)bm * NSZ);
    const float4* t0 = (const float4*)(tgt + ((size_t)b * 3 + 0) * NSZ);
    const float4* t1 = (const float4*)(tgt + ((size_t)b * 3 + 1) * NSZ);
    const float4* t2 = (const float4*)(tgt + ((size_t)b * 3 + 2) * NSZ);

    int t = threadIdx.x;
    float4 kk = Krow[t];
    float4 vv = vrow[t];
    float4 p;
    p.x = uu * kk.x * vv.x;
    p.y = uu * kk.y * vv.y;
    p.z = uu * kk.z * vv.z;
    p.w = uu * kk.w * vv.w;
    Prow[t] = p;

    float4 a0 = t0[t], a1 = t1[t], a2 = t2[t];
    float rs = p.x + p.y + p.z + p.w;
    float w0 = p.x * a0.x + p.y * a0.y + p.z * a0.z + p.w * a0.w;
    float w1 = p.x * a1.x + p.y * a1.y + p.z * a1.z + p.w * a1.w;
    float w2 = p.x * a2.x + p.y * a2.y + p.z * a2.z + p.w * a2.w;

    rs = blockReduceB(rs, sred);
    w0 = blockReduceB(w0, sred);
    w1 = blockReduceB(w1, sred);
    w2 = blockReduceB(w2, sred);
    if (threadIdx.x == 0) {
        g_rowS[bm] = rs;
        float inv = 1.0f / (rs + 1e-6f);
        g_wref[bm * 3 + 0] = w0 * inv;
        g_wref[bm * 3 + 1] = w1 * inv;
        g_wref[bm * 3 + 2] = w2 * inv;
    }
}

// ---------------- per-batch centroids + covariance ----------------
__global__ void cov_kernel(const float* __restrict__ src) {
    __shared__ float sred[32];
    int b = blockIdx.x;
    int t = threadIdx.x;

    float s = 0.0f;
    for (int m = t; m < MSZ; m += 256) s += g_rowS[b * MSZ + m];
    float S = blockReduceB(s, sred);
    float inv = 1.0f / (S + 1e-6f);

    float ca[3] = {0, 0, 0}, cb[3] = {0, 0, 0};
    for (int m = t; m < MSZ; m += 256) {
        float w = g_rowS[b * MSZ + m] * inv;
        #pragma unroll
        for (int d = 0; d < 3; d++) {
            ca[d] += w * src[((size_t)b * 3 + d) * MSZ + m];
            cb[d] += w * g_wref[(b * MSZ + m) * 3 + d];
        }
    }
    float CA[3], CB[3];
    #pragma unroll
    for (int d = 0; d < 3; d++) CA[d] = blockReduceB(ca[d], sred);
    #pragma unroll
    for (int d = 0; d < 3; d++) CB[d] = blockReduceB(cb[d], sred);

    float cv[9] = {0, 0, 0, 0, 0, 0, 0, 0, 0};
    for (int m = t; m < MSZ; m += 256) {
        float w = g_rowS[b * MSZ + m] * inv;
        float ac[3], bc[3];
        #pragma unroll
        for (int d = 0; d < 3; d++) {
            ac[d] = src[((size_t)b * 3 + d) * MSZ + m] - CA[d];
            bc[d] = g_wref[(b * MSZ + m) * 3 + d] - CB[d];
        }
        #pragma unroll
        for (int i = 0; i < 3; i++)
            #pragma unroll
            for (int j = 0; j < 3; j++)
                cv[i * 3 + j] += ac[i] * bc[j] * w;
    }
    #pragma unroll
    for (int k = 0; k < 9; k++) {
        float r = blockReduceB(cv[k], sred);
        if (t == 0) g_cov[b * 9 + k] = r;
    }
    if (t == 0) {
        #pragma unroll
        for (int d = 0; d < 3; d++) { g_ca[b * 3 + d] = CA[d]; g_cb[b * 3 + d] = CB[d]; }
    }
}

// ---------------- 3x3 SVD (fp64 Jacobi) + Kabsch R,t ----------------
__global__ void svd_kernel(float* __restrict__ out) {
    int b = threadIdx.x;
    if (b >= BATCH) return;

    double A[3][3];
    #pragma unroll
    for (int i = 0; i < 3; i++)
        #pragma unroll
        for (int j = 0; j < 3; j++)
            A[i][j] = (double)g_cov[b * 9 + i * 3 + j];

    double S[3][3];
    #pragma unroll
    for (int i = 0; i < 3; i++)
        #pragma unroll
        for (int j = 0; j < 3; j++) {
            double acc = 0.0;
            #pragma unroll
            for (int k = 0; k < 3; k++) acc += A[k][i] * A[k][j];
            S[i][j] = acc;
        }

    double V[3][3] = {{1, 0, 0}, {0, 1, 0}, {0, 0, 1}};
    const int PP[3] = {0, 0, 1};
    const int QQ[3] = {1, 2, 2};
    for (int sweep = 0; sweep < 20; sweep++) {
        for (int r = 0; r < 3; r++) {
            int p = PP[r], q = QQ[r];
            double apq = S[p][q];
            if (apq == 0.0) continue;
            double theta = (S[q][q] - S[p][p]) / (2.0 * apq);
            double tt = copysign(1.0, theta) / (fabs(theta) + sqrt(1.0 + theta * theta));
            double c = 1.0 / sqrt(1.0 + tt * tt);
            double sn = tt * c;
            for (int k = 0; k < 3; k++) {
                double skp = S[k][p], skq = S[k][q];
                S[k][p] = c * skp - sn * skq;
                S[k][q] = sn * skp + c * skq;
            }
            for (int k = 0; k < 3; k++) {
                double spk = S[p][k], sqk = S[q][k];
                S[p][k] = c * spk - sn * sqk;
                S[q][k] = sn * spk + c * sqk;
            }
            for (int k = 0; k < 3; k++) {
                double vkp = V[k][p], vkq = V[k][q];
                V[k][p] = c * vkp - sn * vkq;
                V[k][q] = sn * vkp + c * vkq;
            }
        }
    }

    double ev[3] = {S[0][0], S[1][1], S[2][2]};
    int idx[3] = {0, 1, 2};
    for (int i = 0; i < 2; i++)
        for (int j = i + 1; j < 3; j++)
            if (ev[idx[j]] > ev[idx[i]]) { int tmp = idx[i]; idx[i] = idx[j]; idx[j] = tmp; }

    double Vs[3][3];
    #pragma unroll
    for (int k = 0; k < 3; k++)
        for (int i = 0; i < 3; i++)
            Vs[k][i] = V[k][idx[i]];

    double U[3][3];
    double nrm[3];
    for (int i = 0; i < 3; i++) {
        double u0 = A[0][0] * Vs[0][i] + A[0][1] * Vs[1][i] + A[0][2] * Vs[2][i];
        double u1 = A[1][0] * Vs[0][i] + A[1][1] * Vs[1][i] + A[1][2] * Vs[2][i];
        double u2 = A[2][0] * Vs[0][i] + A[2][1] * Vs[1][i] + A[2][2] * Vs[2][i];
        double nm = sqrt(u0 * u0 + u1 * u1 + u2 * u2);
        nrm[i] = nm;
        double in = (nm > 1e-300) ? 1.0 / nm : 0.0;
        U[0][i] = u0 * in; U[1][i] = u1 * in; U[2][i] = u2 * in;
    }
    if (nrm[2] < 1e-12 * fmax(nrm[0], 1e-300)) {
        U[0][2] = U[1][0] * U[2][1] - U[2][0] * U[1][1];
        U[1][2] = U[2][0] * U[0][1] - U[0][0] * U[2][1];
        U[2][2] = U[0][0] * U[1][1] - U[1][0] * U[0][1];
    }

    double R[3][3];
    for (int i = 0; i < 3; i++)
        for (int j = 0; j < 3; j++)
            R[i][j] = Vs[i][0] * U[j][0] + Vs[i][1] * U[j][1] + Vs[i][2] * U[j][2];

    double det = R[0][0] * (R[1][1] * R[2][2] - R[1][2] * R[2][1])
               - R[0][1] * (R[1][0] * R[2][2] - R[1][2] * R[2][0])
               + R[0][2] * (R[1][0] * R[2][1] - R[1][1] * R[2][0]);
    if (!(det > 0.0)) {
        for (int i = 0; i < 3; i++)
            for (int j = 0; j < 3; j++)
                R[i][j] -= 2.0 * Vs[i][2] * U[j][2];
    }

    double ca[3] = {(double)g_ca[b * 3], (double)g_ca[b * 3 + 1], (double)g_ca[b * 3 + 2]};
    double cb[3] = {(double)g_cb[b * 3], (double)g_cb[b * 3 + 1], (double)g_cb[b * 3 + 2]};
    double tv[3];
    for (int i = 0; i < 3; i++)
        tv[i] = -(R[i][0] * ca[0] + R[i][1] * ca[1] + R[i][2] * ca[2]) + cb[i];

    for (int i = 0; i < 3; i++)
        for (int j = 0; j < 3; j++)
            out[b * 9 + i * 3 + j] = (float)R[i][j];
    for (int i = 0; i < 3; i++)
        out[288 + b * 3 + i] = (float)tv[i];
}

// ---------------- launch ----------------
extern "C" void kernel_launch(void* const* d_in, const int* in_sizes, int n_in,
                              void* d_out, int out_size) {
    const float* src_emb = (const float*)d_in[0];
    const float* tgt_emb = (const float*)d_in[1];
    const float* src     = (const float*)d_in[2];
    const float* tgt     = (const float*)d_in[3];
    const float* lptr    = (const float*)d_in[4];
    const float* rptr    = (const float*)d_in[5];
    float* out = (float*)d_out;
    float* Pout = out + BATCH * 9 + BATCH * 3;

    float* dn1; cudaGetSymbolAddress((void**)&dn1, g_n1);
    float* dn2; cudaGetSymbolAddress((void**)&dn2, g_n2);

    // launch order keeps gemm_mma_kernel as the 4th launch (ncu sample slot)
    init_uv_kernel<<<(BATCH * MSZ) / 256, 256>>>();
    norms_kernel<<<(BATCH * MSZ) / 256, 256>>>(src_emb, dn1);
    norms_kernel<<<(BATCH * NSZ) / 256, 256>>>(tgt_emb, dn2);

    dim3 ggrid(NSZ / 128, MSZ / 128, BATCH);
    gemm_mma_kernel<<<ggrid, 256>>>(src_emb, tgt_emb, lptr);

    for (int it = 0; it < SINK_ITERS; it++) {
        dim3 sgrid(MSZ / 32, BATCH);
        sink_fused_kernel<<<sgrid, 256>>>(lptr, rptr);
        sink_vpow_kernel<<<(BATCH * NSZ) / 256, 256>>>(lptr, rptr);
    }

    compute_P_kernel<<<BATCH * MSZ, 256>>>(tgt, Pout);
    cov_kernel<<<BATCH, 256>>>(src);
    svd_kernel<<<1, 32>>>(out);
}